// round 14
// baseline (speedup 1.0000x reference)
#include <cuda_runtime.h>
#include <cuda_pipeline.h>
#include <cstdint>

// OverlapPatchEmbed: x (64,3,224,224) fp32 -> out (64,729,3,256) fp32.
// 16x16 patches, stride 8, 27x27 patches per image.
//
// R14: A/B isolation of the store cache policy. Identical to R13 except
// stores are plain st.global (default policy) instead of __stcs.
// Rationale: four structurally different kernels all pin at ~27.7us ncu
// with L2 at ~50% of theoretical == ~100% of the HW-measured practical
// LTS ceiling (~6300 B/cyc); the write path (143MB SM->L2 + 143MB
// writeback) dominates and is irreducible. __stcs has been present since
// R2 and never isolated — if evict-first writeback scheduling is
// fragmenting DRAM write efficiency, this round shows it; if flat, the
// write-path floor theory is confirmed.
//
// Structure (unchanged from R13): CTA = (b, c, 3-band group), 32 rows
// loaded once via cp.async (read amp 1.33x), one barrier, then 81
// patches stored as contiguous coalesced float4 chunks. Smem pitch 60 f4
// keeps the patch gather LDS.128 conflict-free ((4ky+kx4) mod 8 distinct
// per 8-lane phase).

static constexpr int B  = 64;
static constexpr int C  = 3;
static constexpr int H  = 224;
static constexpr int W  = 224;
static constexpr int P  = 16;
static constexpr int S  = 8;
static constexpr int N  = 27;
static constexpr int G  = 3;              // py bands per CTA
static constexpr int NG = N / G;          // 9 groups

static constexpr int ROWS_PER_CTA = G * S + S;   // 32 rows
static constexpr int W_F4     = W / 4;           // 56
static constexpr int PITCH_F4 = 60;              // conflict-free pitch
static constexpr int SMEM_F4  = ROWS_PER_CTA * PITCH_F4;  // 1920 f4 = 30720 B

static constexpr int THREADS  = 192;
static constexpr int LOAD_F4  = ROWS_PER_CTA * W_F4;      // 1792
static constexpr int LOAD_ITERS = (LOAD_F4 + THREADS - 1) / THREADS;   // 10
static constexpr int BAND_F4  = N * P * P / 4;            // 1728 per band
static constexpr int STORE_ITERS = BAND_F4 / THREADS;     // 9 exact

__global__ __launch_bounds__(THREADS)
void overlap_patch_kernel(const float4* __restrict__ x,
                          float4* __restrict__ out)
{
    __shared__ float4 sm[SMEM_F4];   // 30.7 KB

    const int tid = threadIdx.x;
    int bx = blockIdx.x;
    const int c  = bx % C;
    bx /= C;
    const int gy = bx % NG;          // vertical group
    const int b  = bx / NG;

    // ---- Load 32 rows of channel c starting at row gy*24 ----
    const float4* g = x + ((int64_t)(b * C + c) * H + gy * (G * S)) * W_F4;
    #pragma unroll
    for (int k = 0; k < LOAD_ITERS; k++) {
        int i = tid + k * THREADS;              // [0, 1792)
        if (i < LOAD_F4) {
            int row = i / W_F4;
            int col = i - row * W_F4;
            __pipeline_memcpy_async(&sm[row * PITCH_F4 + col],
                                    &g[row * W_F4 + col], 16);
        }
    }
    __pipeline_commit();
    __pipeline_wait_prior(0);
    __syncthreads();                 // the ONLY barrier in this CTA

    // ---- Store 3 bands x 27 patches x 64 float4 ----
    #pragma unroll
    for (int j = 0; j < G; j++) {
        const int py = gy * G + j;
        const int64_t obase = ((int64_t)(b * (N * N) + py * N) * C + c) * (P * P / 4);
        const int rbase = j * S;     // smem row offset for this band

        #pragma unroll
        for (int k = 0; k < STORE_ITERS; k++) {
            int idx    = tid + k * THREADS;     // [0, 1728)
            int px     = idx >> 6;
            int within = idx & 63;
            int kx4    = within & 3;
            int ky     = within >> 2;

            float4 v = sm[(rbase + ky) * PITCH_F4 + px * 2 + kx4];
            out[obase + (int64_t)px * (C * P * P / 4) + within] = v;   // plain STG (A/B vs __stcs)
        }
    }
}

extern "C" void kernel_launch(void* const* d_in, const int* in_sizes, int n_in,
                              void* d_out, int out_size)
{
    const float4* x = (const float4*)d_in[0];
    float4* out = (float4*)d_out;

    overlap_patch_kernel<<<B * C * NG, THREADS>>>(x, out);   // 1728 CTAs
}